// round 4
// baseline (speedup 1.0000x reference)
#include <cuda_runtime.h>
#include <cuda_bf16.h>
#include <stdint.h>

// Exact Euclidean distance transform (matches the Meijster-style reference)
// on a 1536x1536 binary mask.
//
// Kernel 1 (pack): column-packed background bitmap, float4 loads + 4 ballots
//   per row, each lane assembles 4 column words, 128-bit stores.
//   colbits[w*C + j] bit b == (mask[(w*32+b)*C + j] == 0). 288 KB, L2-resident.
//
// Kernel 2 (edt, one 512-thread block per row):
//   phase 1: vertical nearest-background. Three bitmap words (wi-1, wi, wi+1)
//     form two 64-bit windows guaranteeing +/-32 rows of coverage for any bit
//     position -> branch-free ffsll/clzll; cross-word expansion loop is
//     warp-voted and essentially never taken (P ~ 2^-32 for a random mask).
//     Cap 3072 (= R+C) when the column has no background at all.
//   phase 2: horizontal min-plus with exact early exit (t^2 >= best cannot
//     improve since g2 >= 0), on a BIG^2-padded shared row -> no bounds checks.
//     Pad candidates are BIG^2 + t^2 > BIG^2 >= the t=0 candidate, so they are
//     never selected: exact.
//
// All quantities (g^2 <= 3072^2, t^2, sums < 2^24) are integers exactly
// representable in fp32. Final sqrt via x*rsqrt(x) (error ~1e-7 << 1e-3 tol).

#define R_DIM 1536
#define C_DIM 1536
#define W_DIM (R_DIM / 32)     // 48 words per column
#define BIG_I (R_DIM + C_DIM)
#define BIGF2 ((float)(BIG_I) * (float)(BIG_I))   // 3072^2 = 9437184 < 2^24
#define EDT_T 512              // threads per edt block
#define JPT   (C_DIM / EDT_T)  // 3 columns per thread
#define PAD   C_DIM

__device__ uint32_t g_colbits[W_DIM * C_DIM];

// One warp per 32-row x 128-col tile. grid(12, 6), block 256 (8 warps).
__global__ __launch_bounds__(256) void pack_kernel(const float4* __restrict__ mask4)
{
    const int lane = threadIdx.x & 31;
    const int warp = threadIdx.x >> 5;
    const int wrow = blockIdx.y * 8 + warp;        // word-row (0..47)
    const int col0 = blockIdx.x * 128;

    const float4* p = mask4 + (size_t)(wrow * 32) * (C_DIM / 4) + col0 / 4 + lane;

    uint32_t w0 = 0, w1 = 0, w2 = 0, w3 = 0;
    #pragma unroll 8
    for (int r = 0; r < 32; ++r) {
        const float4 v = p[r * (C_DIM / 4)];
        const uint32_t b0 = __ballot_sync(0xffffffffu, v.x == 0.0f);
        const uint32_t b1 = __ballot_sync(0xffffffffu, v.y == 0.0f);
        const uint32_t b2 = __ballot_sync(0xffffffffu, v.z == 0.0f);
        const uint32_t b3 = __ballot_sync(0xffffffffu, v.w == 0.0f);
        w0 |= ((b0 >> lane) & 1u) << r;
        w1 |= ((b1 >> lane) & 1u) << r;
        w2 |= ((b2 >> lane) & 1u) << r;
        w3 |= ((b3 >> lane) & 1u) << r;
    }
    uint4 o; o.x = w0; o.y = w1; o.z = w2; o.w = w3;
    *reinterpret_cast<uint4*>(&g_colbits[wrow * C_DIM + col0 + lane * 4]) = o;
}

__global__ __launch_bounds__(EDT_T) void edt_kernel(float* __restrict__ out)
{
    const int row = blockIdx.x;
    const int tid = threadIdx.x;
    const int wi  = row >> 5;
    const int bi  = row & 31;

    __shared__ float g2s[C_DIM + 2 * PAD];
    float* const s = g2s + PAD;

    // fill pads with BIG^2 sentinels (never selected; keeps inner loop checkless)
    #pragma unroll
    for (int u = 0; u < JPT; ++u) {
        g2s[tid + u * EDT_T] = BIGF2;
        g2s[PAD + C_DIM + tid + u * EDT_T] = BIGF2;
    }

    // ---- phase 1: vertical nearest background, 64-bit windows ----
    const uint32_t* base = g_colbits + wi * C_DIM;
    uint32_t lo[JPT], mid[JPT], hi[JPT];
    #pragma unroll
    for (int u = 0; u < JPT; ++u) {
        const int j = tid + u * EDT_T;
        mid[u] = base[j];
        lo[u]  = (wi > 0)         ? base[j - C_DIM] : 0u;
        hi[u]  = (wi < W_DIM - 1) ? base[j + C_DIM] : 0u;
    }

    #pragma unroll
    for (int u = 0; u < JPT; ++u) {
        const int j = tid + u * EDT_T;

        // dn bit k = row+k (k = 0 .. 63-bi);  up bit 63-k = row-k (k = 0 .. 32+bi)
        const uint64_t dn = ((((uint64_t)hi[u]  << 32) | mid[u]) >> bi);
        const uint64_t up = ((((uint64_t)mid[u] << 32) | lo[u]) << (31 - bi));

        int best = BIG_I;
        if (dn) best = __ffsll((long long)dn) - 1;
        if (up) best = min(best, __clzll((long long)up));

        // rare exact expansion beyond the +/-32 guaranteed window (warp-voted)
        const bool need = (best > 63 - bi) || (best > 32 + bi);
        if (__any_sync(0xffffffffu, need)) {
            int wd = wi + 2, dn_off = 64 - bi;
            int wu = wi - 2, up_off = 33 + bi;
            while ((wd < W_DIM && dn_off < best) || (wu >= 0 && up_off < best)) {
                if (wd < W_DIM && dn_off < best) {
                    const uint32_t x = g_colbits[wd * C_DIM + j];
                    if (x) best = min(best, dn_off + __ffs(x) - 1);
                    ++wd; dn_off += 32;
                } else wd = W_DIM;
                if (wu >= 0 && up_off < best) {
                    const uint32_t x = g_colbits[wu * C_DIM + j];
                    if (x) best = min(best, up_off + __clz(x));
                    --wu; up_off += 32;
                } else wu = -1;
            }
        }

        const float g = (float)best;
        s[j] = g * g;
    }

    __syncthreads();

    // ---- phase 2: horizontal windowed min-plus (exact early exit, no bounds) ----
    #pragma unroll
    for (int u = 0; u < JPT; ++u) {
        const int j = tid + u * EDT_T;
        float best = s[j];
        float t2 = 1.0f, inc = 3.0f;   // t^2, then +=(2t+1)
        int t = 1;
        #pragma unroll 1
        while (t2 < best) {
            best = fminf(best, s[j - t] + t2);
            best = fminf(best, s[j + t] + t2);
            t2 += inc; inc += 2.0f; ++t;
        }
        const float d = (best > 0.0f) ? best * __frsqrt_rn(best) : 0.0f;
        out[row * C_DIM + j] = d;
    }
}

extern "C" void kernel_launch(void* const* d_in, const int* in_sizes, int n_in,
                              void* d_out, int out_size) {
    const float4* mask4 = (const float4*)d_in[0];
    float* out = (float*)d_out;

    dim3 pgrid(C_DIM / 128, W_DIM / 8);   // (12, 6)
    pack_kernel<<<pgrid, 256>>>(mask4);
    edt_kernel<<<R_DIM, EDT_T>>>(out);
}